// round 3
// baseline (speedup 1.0000x reference)
#include <cuda_runtime.h>
#include <cuda_bf16.h>
#include <math.h>
#include <float.h>

// Problem constants
#define NB 16
#define CH 256
#define HH 64
#define WW 64
#define NE 1024
#define NTOK (NB*HH*WW)          // 65536
#define ZQ_ELEMS (NB*CH*HH*WW)   // 16777216
#define NBLK 1024                // one block per (b,h)

// Scratch (device globals; no allocations allowed)
__device__ float g_enorm[NE];
__device__ int   g_idx[NTOK];
__device__ float g_loss_partial[NBLK];
__device__ int   g_counts[NE];

// ---------------------------------------------------------------------------
// Kernel A: ||e_j||^2 per codebook row (sequential fp32, rounded mul then add,
// matching sum(e*e)); also zero the histogram. 1024 blocks x 32 threads:
// thread 0 of each block does the sequential sum (order-exactness; cheap).
// ---------------------------------------------------------------------------
__global__ void k_enorm(const float* __restrict__ emb) {
    __shared__ float s[256];
    int j = blockIdx.x, t = threadIdx.x;
    // stage row (coalesced)
    for (int c = t; c < CH; c += 32) s[c] = emb[(size_t)j * CH + c];
    __syncthreads();
    if (t == 0) {
        float acc = 0.0f;
        for (int c = 0; c < CH; c++)
            acc = __fadd_rn(acc, __fmul_rn(s[c], s[c]));
        g_enorm[j] = acc;
        g_counts[j] = 0;
    }
}

// ---------------------------------------------------------------------------
// Kernel B: fused distance GEMM + argmin, replicating reference numerics:
//   d(w,j) = fl( fl(s1_w + enorm_j) - 2*G(w,j) )
// G accumulated as a sequential ascending-k fp32 FMA chain (k = 0..255).
// Tie-break: lowest index (jnp.argmin first-occurrence).
// Block = one (b,h): 64 tokens. Threads 16x16, each 4 tokens x 4 codes.
// ---------------------------------------------------------------------------
__global__ void k_dist(const float* __restrict__ z, const float* __restrict__ emb) {
    extern __shared__ float sm[];
    float* As = sm;            // [256][64]  A[k][w]
    float* Bs = sm + 16384;    // [64][65]   B[code][kk] (padded)
    __shared__ float s_s1[64];

    const int tid = threadIdx.x;
    const int tx = tid & 15;   // token group
    const int ty = tid >> 4;   // code group
    const int bid = blockIdx.x;
    const int b = bid >> 6, h = bid & 63;

    const float* zb = z + (size_t)b * CH * (HH * WW) + (size_t)h * WW;

    // Load A tile: As[c*64 + w] = z[b][c][h][w]  (fully coalesced)
#pragma unroll
    for (int i = 0; i < 64; i++) {
        int l = i * 256 + tid;       // l = c*64 + w
        int c = l >> 6, w = l & 63;
        As[l] = zb[(size_t)c * (HH * WW) + w];
    }
    __syncthreads();

    // s1_w = sum_c z^2 (rounded mul + sequential add, like sum(zf*zf))
    if (tid < 64) {
        float acc = 0.0f;
        for (int c = 0; c < CH; c++) {
            float v = As[c * 64 + tid];
            acc = __fadd_rn(acc, __fmul_rn(v, v));
        }
        s_s1[tid] = acc;
    }
    __syncthreads();

    float my_s1[4];
#pragma unroll
    for (int m = 0; m < 4; m++) my_s1[m] = s_s1[tx * 4 + m];

    float bd[4];
    int bi[4];
#pragma unroll
    for (int m = 0; m < 4; m++) { bd[m] = FLT_MAX; bi[m] = 0; }

    const float4* As4 = reinterpret_cast<const float4*>(As);

    for (int jt = 0; jt < 16; jt++) {
        float acc[4][4];
#pragma unroll
        for (int m = 0; m < 4; m++)
#pragma unroll
            for (int e = 0; e < 4; e++) acc[m][e] = 0.0f;

        for (int kc = 0; kc < 4; kc++) {
            __syncthreads();
            // Load B tile: Bs[code][kk] = emb[jt*64+code][kc*64+kk]
#pragma unroll
            for (int i = 0; i < 16; i++) {
                int l = i * 256 + tid;
                int code = l >> 6, kk = l & 63;
                Bs[code * 65 + kk] = emb[(size_t)(jt * 64 + code) * CH + kc * 64 + kk];
            }
            __syncthreads();
            // Sequential ascending-k FMA chain per accumulator (numerics-critical)
#pragma unroll 16
            for (int kk = 0; kk < 64; kk++) {
                int k = kc * 64 + kk;
                float4 a = As4[(k << 4) + tx];
                float b0 = Bs[(ty * 4 + 0) * 65 + kk];
                float b1 = Bs[(ty * 4 + 1) * 65 + kk];
                float b2 = Bs[(ty * 4 + 2) * 65 + kk];
                float b3 = Bs[(ty * 4 + 3) * 65 + kk];
                acc[0][0] = __fmaf_rn(a.x, b0, acc[0][0]);
                acc[0][1] = __fmaf_rn(a.x, b1, acc[0][1]);
                acc[0][2] = __fmaf_rn(a.x, b2, acc[0][2]);
                acc[0][3] = __fmaf_rn(a.x, b3, acc[0][3]);
                acc[1][0] = __fmaf_rn(a.y, b0, acc[1][0]);
                acc[1][1] = __fmaf_rn(a.y, b1, acc[1][1]);
                acc[1][2] = __fmaf_rn(a.y, b2, acc[1][2]);
                acc[1][3] = __fmaf_rn(a.y, b3, acc[1][3]);
                acc[2][0] = __fmaf_rn(a.z, b0, acc[2][0]);
                acc[2][1] = __fmaf_rn(a.z, b1, acc[2][1]);
                acc[2][2] = __fmaf_rn(a.z, b2, acc[2][2]);
                acc[2][3] = __fmaf_rn(a.z, b3, acc[2][3]);
                acc[3][0] = __fmaf_rn(a.w, b0, acc[3][0]);
                acc[3][1] = __fmaf_rn(a.w, b1, acc[3][1]);
                acc[3][2] = __fmaf_rn(a.w, b2, acc[3][2]);
                acc[3][3] = __fmaf_rn(a.w, b3, acc[3][3]);
            }
        }
        // Fold tile into running argmin with reference-identical rounding:
        // d = fl( fl(s1 + enorm) - 2*G )
#pragma unroll
        for (int e = 0; e < 4; e++) {
            int j = jt * 64 + ty * 4 + e;
            float en = __ldg(&g_enorm[j]);
#pragma unroll
            for (int m = 0; m < 4; m++) {
                float t0 = __fadd_rn(my_s1[m], en);
                float dd = __fsub_rn(t0, __fmul_rn(2.0f, acc[m][e]));
                if (dd < bd[m] || (dd == bd[m] && j < bi[m])) {
                    bd[m] = dd;
                    bi[m] = j;
                }
            }
        }
    }

    // Cross-thread reduction over the 16 code-groups per token (reuse Bs)
    __syncthreads();
    float* sd = Bs;               // 64*16 floats
    int* si = (int*)(Bs + 1024);  // 64*16 ints
#pragma unroll
    for (int m = 0; m < 4; m++) {
        int tok = tx * 4 + m;
        sd[tok * 16 + ty] = bd[m];
        si[tok * 16 + ty] = bi[m];
    }
    __syncthreads();
    if (tid < 64) {
        float best = sd[tid * 16];
        int besti = si[tid * 16];
#pragma unroll
        for (int q = 1; q < 16; q++) {
            float dd = sd[tid * 16 + q];
            int jj = si[tid * 16 + q];
            if (dd < best || (dd == best && jj < besti)) { best = dd; besti = jj; }
        }
        g_idx[bid * 64 + tid] = besti;
    }
}

// ---------------------------------------------------------------------------
// Kernel C: gather z_q with straight-through arithmetic (out = z + (z_q - z)),
// per-block SSE partial (deterministic), histogram, idx tail writes.
// ---------------------------------------------------------------------------
__global__ void k_gather(const float* __restrict__ z, const float* __restrict__ emb,
                         float* __restrict__ out, int out_size) {
    extern __shared__ float sm[];   // s_emb [64][257]
    __shared__ int s_idx[64];
    __shared__ float sred[256];

    const int tid = threadIdx.x;
    const int bid = blockIdx.x;
    const int b = bid >> 6, h = bid & 63;

    if (tid < 64) s_idx[tid] = g_idx[bid * 64 + tid];
    __syncthreads();

    // Stage the 64 selected codebook rows into smem (coalesced per row)
#pragma unroll
    for (int i = 0; i < 64; i++) {
        sm[i * 257 + tid] = emb[(size_t)s_idx[i] * CH + tid];
    }
    if (tid < 64) atomicAdd(&g_counts[s_idx[tid]], 1);
    __syncthreads();

    const float* zb = z + (size_t)b * CH * (HH * WW) + (size_t)h * WW;
    float* ob = out + (size_t)b * CH * (HH * WW) + (size_t)h * WW;

    float accum = 0.0f;
#pragma unroll
    for (int i = 0; i < 64; i++) {
        int l = i * 256 + tid;
        int c = l >> 6, w = l & 63;
        float zq = sm[w * 257 + c];
        size_t off = (size_t)c * (HH * WW) + w;
        float zv = zb[off];
        float d = __fsub_rn(zq, zv);           // z_q - z
        ob[off] = __fadd_rn(zv, d);            // STE: z + (z_q - z)
        accum = __fmaf_rn(d, d, accum);
    }
    sred[tid] = accum;
    __syncthreads();
    for (int s = 128; s > 0; s >>= 1) {
        if (tid < s) sred[tid] += sred[tid + s];
        __syncthreads();
    }
    if (tid == 0) g_loss_partial[bid] = sred[0];

    // idx tail (as float), guarded by out_size
    if (tid < 64) {
        int n = bid * 64 + tid;
        long long pos = (long long)ZQ_ELEMS + 2 + n;
        if (pos < (long long)out_size) out[pos] = (float)s_idx[tid];
    }
}

// ---------------------------------------------------------------------------
// Kernel D: finalize loss + perplexity (deterministic single-block reduce).
// loss = mean + BETA*mean, as the reference sums two means.
// ---------------------------------------------------------------------------
__global__ void k_final(float* __restrict__ out, int out_size) {
    __shared__ float sl[1024];
    __shared__ float se[1024];
    int t = threadIdx.x;
    float lp = g_loss_partial[t];
    float em = (float)g_counts[t] / (float)NTOK;
    float ent = -em * logf(em + 1e-10f);
    sl[t] = lp;
    se[t] = ent;
    __syncthreads();
    for (int s = 512; s > 0; s >>= 1) {
        if (t < s) { sl[t] += sl[t + s]; se[t] += se[t + s]; }
        __syncthreads();
    }
    if (t == 0) {
        float m = sl[0] / (float)ZQ_ELEMS;
        if (out_size > ZQ_ELEMS)     out[ZQ_ELEMS]     = __fmaf_rn(0.25f, m, m);
        if (out_size > ZQ_ELEMS + 1) out[ZQ_ELEMS + 1] = expf(se[0]);
    }
}

// ---------------------------------------------------------------------------
extern "C" void kernel_launch(void* const* d_in, const int* in_sizes, int n_in,
                              void* d_out, int out_size) {
    const float* z = (const float*)d_in[0];
    const float* emb = (const float*)d_in[1];
    // Defensive input ordering by size (z has 16.7M elements, emb 262144)
    if (n_in >= 2 && in_sizes[0] == NE * CH) {
        const float* t = z; z = emb; emb = t;
    }
    float* out = (float*)d_out;

    const int SMEM_DIST = (16384 + 64 * 65) * 4;   // 82176 B
    const int SMEM_GATH = 64 * 257 * 4;            // 65792 B
    cudaFuncSetAttribute(k_dist, cudaFuncAttributeMaxDynamicSharedMemorySize, SMEM_DIST);
    cudaFuncSetAttribute(k_gather, cudaFuncAttributeMaxDynamicSharedMemorySize, SMEM_GATH);

    k_enorm<<<NE, 32>>>(emb);
    k_dist<<<NBLK, 256, SMEM_DIST>>>(z, emb);
    k_gather<<<NBLK, 256, SMEM_GATH>>>(z, emb, out, out_size);
    k_final<<<1, 1024>>>(out, out_size);
}

// round 9
// speedup vs baseline: 1.0471x; 1.0471x over previous
#include <cuda_runtime.h>
#include <math.h>
#include <float.h>

// Problem constants
#define NB 16
#define CH 256
#define HH 64
#define WW 64
#define NE 1024
#define NTOK (NB*HH*WW)          // 65536
#define ZQ_ELEMS (NB*CH*HH*WW)   // 16777216

// k_dist geometry
#define TOKB 32                   // tokens per block
#define CPP  512                  // codes per pass (2 passes)
#define KC   32                   // k-chunk
#define BSTR 516                  // Bs row stride (floats), 129 float4

// Scratch (device globals; no allocations allowed)
__device__ float g_enorm[NE];
__device__ int   g_idx[NTOK];
__device__ float g_loss_partial[1024];
__device__ int   g_counts[NE];

typedef unsigned long long u64;

__device__ __forceinline__ u64 dup2(float x) {
    u64 r; asm("mov.b64 %0, {%1, %1};" : "=l"(r) : "f"(x)); return r;
}
__device__ __forceinline__ void ffma2(u64& d, u64 a, u64 b) {
    asm("fma.rn.f32x2 %0, %1, %2, %3;" : "=l"(d) : "l"(a), "l"(b), "l"(d));
}
__device__ __forceinline__ float2 unpk(u64 v) {
    float2 f; asm("mov.b64 {%0, %1}, %2;" : "=f"(f.x), "=f"(f.y) : "l"(v));
    return f;
}

// ---------------------------------------------------------------------------
// Kernel A: ||e_j||^2 (sequential fp32: rounded mul then add); zero histogram.
// ---------------------------------------------------------------------------
__global__ void k_enorm(const float* __restrict__ emb) {
    __shared__ float s[256];
    int j = blockIdx.x, t = threadIdx.x;
    for (int c = t; c < CH; c += 32) s[c] = emb[(size_t)j * CH + c];
    __syncthreads();
    if (t == 0) {
        float acc = 0.0f;
        for (int c = 0; c < CH; c++)
            acc = __fadd_rn(acc, __fmul_rn(s[c], s[c]));
        g_enorm[j] = acc;
        g_counts[j] = 0;
    }
}

// ---------------------------------------------------------------------------
// Kernel B: fused distance GEMM + argmin using packed fma.rn.f32x2.
// Each 64-bit accumulator holds two independent sequential ascending-k fp32
// FMA chains (two adjacent tokens, same code) -> bitwise identical to scalar.
// Block = 32 tokens. Threads 256: tx=tid&3 (8 tokens), ty=tid>>2 (8 codes),
// 512 codes/pass, 2 passes.
// d = fl( fl(s1 + enorm_j) - 2*G ).
// Tie-break (jnp.argmin first-occurrence): per-thread j strictly ascends so
// strict < suffices; CROSS-THREAD stages need explicit (d==, j<) tie-break
// because j-order is not monotone in ty (two-pass code ownership).
// ---------------------------------------------------------------------------
__global__ void __launch_bounds__(256, 2)
k_dist(const float* __restrict__ z, const float* __restrict__ emb) {
    extern __shared__ float sm[];
    float* As = sm;                    // [256][32]  A[k][tok]   (32 KB)
    float* Bs = sm + 256 * TOKB;       // [KC][BSTR] B[kk][code] (64.5 KB)
    __shared__ float s_s1[TOKB];

    const int tid = threadIdx.x;
    const int tx = tid & 3;
    const int ty = tid >> 2;
    const int bid = blockIdx.x;
    const int bh = bid >> 1;
    const int b = bh >> 6, h = bh & 63;
    const int w0 = (bid & 1) * TOKB;

    const float* zb = z + (size_t)b * CH * 4096 + (size_t)h * 64 + w0;

    // Load A tile (coalesced)
#pragma unroll
    for (int i = 0; i < 32; i++) {
        int l = i * 256 + tid;
        int c = l >> 5, w = l & 31;
        As[c * 32 + w] = zb[(size_t)c * 4096 + w];
    }
    __syncthreads();

    // s1 per token: sequential sum of rounded squares (reference order)
    if (tid < TOKB) {
        float a = 0.0f;
        for (int c = 0; c < CH; c++) {
            float v = As[c * 32 + tid];
            a = __fadd_rn(a, __fmul_rn(v, v));
        }
        s_s1[tid] = a;
    }
    __syncthreads();

    float my_s1[8];
#pragma unroll
    for (int m = 0; m < 8; m++) my_s1[m] = s_s1[tx * 8 + m];

    float bd[8];
    int bi[8];
#pragma unroll
    for (int m = 0; m < 8; m++) { bd[m] = FLT_MAX; bi[m] = 0; }

    const double2* Ad2 = (const double2*)As;   // 8 double2 per k-row
    const float4* Bs4 = (const float4*)Bs;     // 129 float4 per kk-row

    for (int pass = 0; pass < 2; pass++) {
        const int jbase = pass * CPP;
        u64 acc[8][4];
#pragma unroll
        for (int e = 0; e < 8; e++)
#pragma unroll
            for (int p = 0; p < 4; p++) acc[e][p] = 0ull;

        for (int kb = 0; kb < CH; kb += KC) {
            __syncthreads();
            // Fill Bs[kk][code] (transpose of emb rows), float4 gmem reads
#pragma unroll
            for (int i = 0; i < 16; i++) {
                int idx = i * 1024 + tid * 4;
                int code = idx >> 5;          // 0..511
                int kk = idx & 31;            // multiple of 4
                float4 v = *(const float4*)&emb[(size_t)(jbase + code) * CH + kb + kk];
                Bs[(kk + 0) * BSTR + code] = v.x;
                Bs[(kk + 1) * BSTR + code] = v.y;
                Bs[(kk + 2) * BSTR + code] = v.z;
                Bs[(kk + 3) * BSTR + code] = v.w;
            }
            __syncthreads();

#pragma unroll 4
            for (int kk = 0; kk < KC; kk++) {
                const int k = kb + kk;
                double2 da = Ad2[k * 8 + tx * 2];      // tokens 8tx..8tx+3
                double2 db = Ad2[k * 8 + tx * 2 + 1];  // tokens 8tx+4..+7
                u64 a0 = __double_as_longlong(da.x);
                u64 a1 = __double_as_longlong(da.y);
                u64 a2 = __double_as_longlong(db.x);
                u64 a3 = __double_as_longlong(db.y);
                float4 q0 = Bs4[kk * 129 + ty * 2];
                float4 q1 = Bs4[kk * 129 + ty * 2 + 1];
                u64 B0 = dup2(q0.x), B1 = dup2(q0.y), B2 = dup2(q0.z), B3 = dup2(q0.w);
                u64 B4 = dup2(q1.x), B5 = dup2(q1.y), B6 = dup2(q1.z), B7 = dup2(q1.w);
                ffma2(acc[0][0], a0, B0); ffma2(acc[0][1], a1, B0);
                ffma2(acc[0][2], a2, B0); ffma2(acc[0][3], a3, B0);
                ffma2(acc[1][0], a0, B1); ffma2(acc[1][1], a1, B1);
                ffma2(acc[1][2], a2, B1); ffma2(acc[1][3], a3, B1);
                ffma2(acc[2][0], a0, B2); ffma2(acc[2][1], a1, B2);
                ffma2(acc[2][2], a2, B2); ffma2(acc[2][3], a3, B2);
                ffma2(acc[3][0], a0, B3); ffma2(acc[3][1], a1, B3);
                ffma2(acc[3][2], a2, B3); ffma2(acc[3][3], a3, B3);
                ffma2(acc[4][0], a0, B4); ffma2(acc[4][1], a1, B4);
                ffma2(acc[4][2], a2, B4); ffma2(acc[4][3], a3, B4);
                ffma2(acc[5][0], a0, B5); ffma2(acc[5][1], a1, B5);
                ffma2(acc[5][2], a2, B5); ffma2(acc[5][3], a3, B5);
                ffma2(acc[6][0], a0, B6); ffma2(acc[6][1], a1, B6);
                ffma2(acc[6][2], a2, B6); ffma2(acc[6][3], a3, B6);
                ffma2(acc[7][0], a0, B7); ffma2(acc[7][1], a1, B7);
                ffma2(acc[7][2], a2, B7); ffma2(acc[7][3], a3, B7);
            }
        }

        // Fold pass into running argmin (j strictly ascends per thread:
        // strict < keeps first occurrence)
#pragma unroll
        for (int e = 0; e < 8; e++) {
            int j = jbase + ty * 8 + e;
            float en = __ldg(&g_enorm[j]);
#pragma unroll
            for (int p = 0; p < 4; p++) {
                float2 g = unpk(acc[e][p]);
                int m0 = 2 * p, m1 = 2 * p + 1;
                float t0 = __fadd_rn(my_s1[m0], en);
                float d0 = __fsub_rn(t0, __fmul_rn(2.0f, g.x));
                if (d0 < bd[m0]) { bd[m0] = d0; bi[m0] = j; }
                float t1 = __fadd_rn(my_s1[m1], en);
                float d1 = __fsub_rn(t1, __fmul_rn(2.0f, g.y));
                if (d1 < bd[m1]) { bd[m1] = d1; bi[m1] = j; }
            }
        }
    }

    // Cross-thread argmin reduction — EXPLICIT (d, j) lexicographic tie-break
    __syncthreads();
    float* sd = Bs;                      // [32 tok][64 ty]
    int* si = (int*)(Bs + 2048);
    float* sd2 = Bs + 4096;              // [8 seg][32 tok]
    int* si2 = (int*)(Bs + 4096 + 256);
#pragma unroll
    for (int m = 0; m < 8; m++) {
        int tok = tx * 8 + m;
        sd[tok * 64 + ty] = bd[m];
        si[tok * 64 + ty] = bi[m];
    }
    __syncthreads();
    {
        int tok = tid & 31, seg = tid >> 5;
        int base = tok * 64 + seg * 8;
        float best = sd[base]; int bj = si[base];
#pragma unroll
        for (int q = 1; q < 8; q++) {
            float v = sd[base + q];
            int jj = si[base + q];
            if (v < best || (v == best && jj < bj)) { best = v; bj = jj; }
        }
        sd2[seg * 32 + tok] = best;
        si2[seg * 32 + tok] = bj;
    }
    __syncthreads();
    if (tid < 32) {
        float best = sd2[tid]; int bj = si2[tid];
#pragma unroll
        for (int s = 1; s < 8; s++) {
            float v = sd2[s * 32 + tid];
            int jj = si2[s * 32 + tid];
            if (v < best || (v == best && jj < bj)) { best = v; bj = jj; }
        }
        g_idx[bid * 32 + tid] = bj;
    }
}

// ---------------------------------------------------------------------------
// Kernel C: gather z_q with STE arithmetic (out = z + (z_q - z)), per-block
// SSE partial, histogram, idx tail. Block = one (b,h), 256 threads.
// ---------------------------------------------------------------------------
__global__ void k_gather(const float* __restrict__ z, const float* __restrict__ emb,
                         float* __restrict__ out, int out_size) {
    extern __shared__ float sm[];   // s_emb [64][257]
    __shared__ int s_idx[64];
    __shared__ float sred[256];

    const int tid = threadIdx.x;
    const int bid = blockIdx.x;
    const int b = bid >> 6, h = bid & 63;

    if (tid < 64) s_idx[tid] = g_idx[bid * 64 + tid];
    __syncthreads();

#pragma unroll
    for (int i = 0; i < 64; i++) {
        sm[i * 257 + tid] = emb[(size_t)s_idx[i] * CH + tid];
    }
    if (tid < 64) atomicAdd(&g_counts[s_idx[tid]], 1);
    __syncthreads();

    const float* zb = z + (size_t)b * CH * 4096 + (size_t)h * 64;
    float* ob = out + (size_t)b * CH * 4096 + (size_t)h * 64;

    float accum = 0.0f;
#pragma unroll
    for (int i = 0; i < 64; i++) {
        int l = i * 256 + tid;
        int c = l >> 6, w = l & 63;
        float zq = sm[w * 257 + c];
        size_t off = (size_t)c * 4096 + w;
        float zv = zb[off];
        float d = __fsub_rn(zq, zv);
        ob[off] = __fadd_rn(zv, d);            // STE: z + (z_q - z)
        accum = __fmaf_rn(d, d, accum);
    }
    sred[tid] = accum;
    __syncthreads();
    for (int s = 128; s > 0; s >>= 1) {
        if (tid < s) sred[tid] += sred[tid + s];
        __syncthreads();
    }
    if (tid == 0) g_loss_partial[bid] = sred[0];

    if (tid < 64) {
        int n = bid * 64 + tid;
        long long pos = (long long)ZQ_ELEMS + 2 + n;
        if (pos < (long long)out_size) out[pos] = (float)s_idx[tid];
    }
}

// ---------------------------------------------------------------------------
// Kernel D: finalize loss + perplexity.
// ---------------------------------------------------------------------------
__global__ void k_final(float* __restrict__ out, int out_size) {
    __shared__ float sl[1024];
    __shared__ float se[1024];
    int t = threadIdx.x;
    float lp = g_loss_partial[t];
    float em = (float)g_counts[t] / (float)NTOK;
    float ent = -em * logf(em + 1e-10f);
    sl[t] = lp;
    se[t] = ent;
    __syncthreads();
    for (int s = 512; s > 0; s >>= 1) {
        if (t < s) { sl[t] += sl[t + s]; se[t] += se[t + s]; }
        __syncthreads();
    }
    if (t == 0) {
        float m = sl[0] / (float)ZQ_ELEMS;
        if (out_size > ZQ_ELEMS)     out[ZQ_ELEMS]     = __fmaf_rn(0.25f, m, m);
        if (out_size > ZQ_ELEMS + 1) out[ZQ_ELEMS + 1] = expf(se[0]);
    }
}

// ---------------------------------------------------------------------------
extern "C" void kernel_launch(void* const* d_in, const int* in_sizes, int n_in,
                              void* d_out, int out_size) {
    const float* z = (const float*)d_in[0];
    const float* emb = (const float*)d_in[1];
    if (n_in >= 2 && in_sizes[0] == NE * CH) {
        const float* t = z; z = emb; emb = t;
    }
    float* out = (float*)d_out;

    const int SMEM_DIST = (256 * TOKB + KC * BSTR) * 4;   // 98816 B
    const int SMEM_GATH = 64 * 257 * 4;                    // 65792 B
    cudaFuncSetAttribute(k_dist, cudaFuncAttributeMaxDynamicSharedMemorySize, SMEM_DIST);
    cudaFuncSetAttribute(k_gather, cudaFuncAttributeMaxDynamicSharedMemorySize, SMEM_GATH);

    k_enorm<<<NE, 32>>>(emb);
    k_dist<<<2048, 256, SMEM_DIST>>>(z, emb);
    k_gather<<<1024, 256, SMEM_GATH>>>(z, emb, out, out_size);
    k_final<<<1, 1024>>>(out, out_size);
}

// round 13
// speedup vs baseline: 1.2519x; 1.1956x over previous
#include <cuda_runtime.h>
#include <cuda_bf16.h>
#include <math.h>
#include <float.h>

// Problem constants
#define NB 16
#define CH 256
#define HH 64
#define WW 64
#define NE 1024
#define NTOK (NB*HH*WW)          // 65536
#define ZQ_ELEMS (NB*CH*HH*WW)   // 16777216

// Screening geometry
#define ZSTR 264                 // zbf row stride (bf16)
#define ESTR 264                 // esm row stride (bf16)
#define CAP  64                  // max candidates per token
#define MARGIN 5.0e-3f           // >= 2*screen err (1.6e-3 worst case), 3x safety

// Scratch (device globals; no allocations allowed)
__device__ float    g_enorm[NE];
__device__ int      g_idx[NTOK];
__device__ float    g_loss_partial[1024];
__device__ int      g_counts[NE];
__device__ __align__(16) __nv_bfloat16 g_ebf[NE*CH];
__device__ unsigned g_ccnt[NTOK];
__device__ int      g_cand[(size_t)NTOK*CAP];

// Monotonic float<->uint encoding for atomicMin on floats
__device__ __forceinline__ unsigned fenc(float f) {
    unsigned u = __float_as_uint(f);
    return (u & 0x80000000u) ? ~u : (u | 0x80000000u);
}
__device__ __forceinline__ float fdec(unsigned e) {
    unsigned u = (e & 0x80000000u) ? (e & 0x7fffffffu) : ~e;
    return __uint_as_float(u);
}

__device__ __forceinline__ void mma16816(float* d,
    unsigned a0, unsigned a1, unsigned a2, unsigned a3,
    unsigned b0, unsigned b1) {
    asm volatile(
        "mma.sync.aligned.m16n8k16.row.col.f32.bf16.bf16.f32 "
        "{%0,%1,%2,%3},{%4,%5,%6,%7},{%8,%9},{%0,%1,%2,%3};"
        : "+f"(d[0]), "+f"(d[1]), "+f"(d[2]), "+f"(d[3])
        : "r"(a0), "r"(a1), "r"(a2), "r"(a3), "r"(b0), "r"(b1));
}

// ---------------------------------------------------------------------------
// Kernel A: ||e_j||^2 (sequential fp32: rounded mul then add); bf16 copy of
// the codebook; zero histogram.
// ---------------------------------------------------------------------------
__global__ void k_enorm(const float* __restrict__ emb) {
    __shared__ float s[256];
    int j = blockIdx.x, t = threadIdx.x;
    for (int c = t; c < CH; c += 32) s[c] = emb[(size_t)j * CH + c];
    __syncthreads();
    for (int c = t; c < CH; c += 32)
        g_ebf[(size_t)j * CH + c] = __float2bfloat16(s[c]);
    if (t == 0) {
        float acc = 0.0f;
        for (int c = 0; c < CH; c++)
            acc = __fadd_rn(acc, __fmul_rn(s[c], s[c]));
        g_enorm[j] = acc;
        g_counts[j] = 0;
    }
}

// ---------------------------------------------------------------------------
// Kernel B1: tensor-core screening. Block = 64 tokens (one (b,h) row), all
// 1024 codes in 8 passes of 128. 8 warps: wm=wid>>1 (16-token tile),
// wn=wid&1 (64-code half). c~ = enorm_j - 2*G~ (bf16 mma, fp32 accum).
// Keeps every j with c~ <= runningmin + MARGIN as a candidate (guaranteed
// superset of the exact winner).
// ---------------------------------------------------------------------------
__global__ void __launch_bounds__(256, 1)
k_screen(const float* __restrict__ z) {
    extern __shared__ __nv_bfloat16 smb[];
    __nv_bfloat16* zbf = smb;              // [64][ZSTR]
    __nv_bfloat16* esm = smb + 64 * ZSTR;  // [128][ESTR]
    __shared__ unsigned runmin[64];
    __shared__ unsigned scnt[64];
    __shared__ int scand[64 * CAP];

    const int tid = threadIdx.x, lane = tid & 31, wid = tid >> 5;
    const int wm = wid >> 1, wn = wid & 1;
    const int bid = blockIdx.x, b = bid >> 6, h = bid & 63;
    const float* zb = z + (size_t)b * CH * 4096 + (size_t)h * 64;

    // Load + convert z tile -> zbf[token][k] (coalesced gmem reads)
#pragma unroll
    for (int i = 0; i < 64; i++) {
        int l = i * 256 + tid, c = l >> 6, w = l & 63;
        zbf[w * ZSTR + c] = __float2bfloat16(zb[(size_t)c * 4096 + w]);
    }
    if (tid < 64) { runmin[tid] = 0xffffffffu; scnt[tid] = 0u; }

    const int tokr = wm * 16 + (lane >> 2);
    const int kql = (lane & 3) * 2;

    for (int pass = 0; pass < 8; pass++) {
        const int jbase = pass * 128;
        __syncthreads();
        {   // load 128 codebook rows (bf16) into esm
            int row = tid >> 1, half = tid & 1;
            const uint4* src = (const uint4*)(g_ebf + (size_t)(jbase + row) * CH + half * 128);
            uint4* dst = (uint4*)(esm + row * ESTR + half * 128);
#pragma unroll
            for (int i = 0; i < 16; i++) dst[i] = src[i];
        }
        __syncthreads();

        float dacc[8][4];
#pragma unroll
        for (int nt = 0; nt < 8; nt++)
#pragma unroll
            for (int c2 = 0; c2 < 4; c2++) dacc[nt][c2] = 0.0f;

#pragma unroll
        for (int kk = 0; kk < 16; kk++) {
            int kc = kk * 16 + kql;
            unsigned a0 = *(const unsigned*)(zbf + tokr * ZSTR + kc);
            unsigned a1 = *(const unsigned*)(zbf + (tokr + 8) * ZSTR + kc);
            unsigned a2 = *(const unsigned*)(zbf + tokr * ZSTR + kc + 8);
            unsigned a3 = *(const unsigned*)(zbf + (tokr + 8) * ZSTR + kc + 8);
#pragma unroll
            for (int nt = 0; nt < 8; nt++) {
                int code = wn * 64 + nt * 8 + (lane >> 2);
                unsigned b0 = *(const unsigned*)(esm + code * ESTR + kc);
                unsigned b1 = *(const unsigned*)(esm + code * ESTR + kc + 8);
                mma16816(dacc[nt], a0, a1, a2, a3, b0, b1);
            }
        }

        // Epilogue: c~ values, per-token running min, candidate append
        float cv[16], cw[16];
        float m0 = FLT_MAX, m1 = FLT_MAX;
#pragma unroll
        for (int nt = 0; nt < 8; nt++) {
#pragma unroll
            for (int c2 = 0; c2 < 2; c2++) {
                int j = jbase + wn * 64 + nt * 8 + kql + c2;
                float en = __ldg(&g_enorm[j]);
                float v0 = en - 2.0f * dacc[nt][c2];       // row tokr
                float v1 = en - 2.0f * dacc[nt][2 + c2];   // row tokr+8
                cv[nt * 2 + c2] = v0; cw[nt * 2 + c2] = v1;
                m0 = fminf(m0, v0); m1 = fminf(m1, v1);
            }
        }
        m0 = fminf(m0, __shfl_xor_sync(0xffffffffu, m0, 1));
        m0 = fminf(m0, __shfl_xor_sync(0xffffffffu, m0, 2));
        m1 = fminf(m1, __shfl_xor_sync(0xffffffffu, m1, 1));
        m1 = fminf(m1, __shfl_xor_sync(0xffffffffu, m1, 2));
        if ((lane & 3) == 0) {
            atomicMin(&runmin[tokr], fenc(m0));
            atomicMin(&runmin[tokr + 8], fenc(m1));
        }
        __syncthreads();
        float thr0 = fdec(runmin[tokr]) + MARGIN;
        float thr1 = fdec(runmin[tokr + 8]) + MARGIN;
#pragma unroll
        for (int i = 0; i < 16; i++) {
            int j = jbase + wn * 64 + (i >> 1) * 8 + kql + (i & 1);
            if (cv[i] <= thr0) {
                unsigned p = atomicAdd(&scnt[tokr], 1u);
                if (p < CAP) scand[tokr * CAP + p] = j;
            }
            if (cw[i] <= thr1) {
                unsigned p = atomicAdd(&scnt[tokr + 8], 1u);
                if (p < CAP) scand[(tokr + 8) * CAP + p] = j;
            }
        }
    }
    __syncthreads();
    if (tid < 64) g_ccnt[bid * 64 + tid] = scnt[tid];
    for (int i = tid; i < 64 * CAP; i += 256)
        g_cand[(size_t)bid * 64 * CAP + i] = scand[i];
}

// ---------------------------------------------------------------------------
// Kernel B2: exact rescue. Warp per token: recompute the frozen reference
// numerics d = fl(fl(s1+en) - 2*G) (sequential ascending-k fp32 FMA chains)
// for EVERY candidate (strided over lanes — handles cnt up to CAP=64);
// lexicographic (d, j) argmin. Overflow -> full exact scan.
// ---------------------------------------------------------------------------
__global__ void __launch_bounds__(256)
k_exact(const float* __restrict__ z, const float* __restrict__ emb) {
    __shared__ float zrow[8][CH];
    const int tid = threadIdx.x, lane = tid & 31, wid = tid >> 5;
    const int n = blockIdx.x * 8 + wid;
    const int b = n >> 12, h = (n >> 6) & 63, w = n & 63;
    const float* zb = z + (size_t)b * CH * 4096 + (size_t)h * 64 + w;
#pragma unroll
    for (int i = 0; i < 8; i++)
        zrow[wid][lane + 32 * i] = zb[(size_t)(lane + 32 * i) * 4096];
    __syncwarp();

    float s1 = 0.0f;
    for (int k = 0; k < CH; k++) {
        float v = zrow[wid][k];
        s1 = __fadd_rn(s1, __fmul_rn(v, v));
    }

    unsigned cnt = g_ccnt[n];
    float d = FLT_MAX; int bj = 0x7fffffff;
    if (cnt <= CAP) {
        // Strided candidate loop: every candidate evaluated regardless of cnt>32
        for (unsigned p = lane; p < cnt; p += 32) {
            int j = g_cand[(size_t)n * CAP + p];
            const float* e = emb + (size_t)j * CH;
            float acc = 0.0f;
            for (int k = 0; k < CH; k++)
                acc = __fmaf_rn(zrow[wid][k], __ldg(&e[k]), acc);
            float dd = __fsub_rn(__fadd_rn(s1, __ldg(&g_enorm[j])), __fmul_rn(2.0f, acc));
            if (dd < d || (dd == d && j < bj)) { d = dd; bj = j; }
        }
    } else {
        // overflow fallback: exact full scan (deterministic, rare)
        for (int t = 0; t < NE / 32; t++) {
            int j = t * 32 + lane;
            const float* e = emb + (size_t)j * CH;
            float acc = 0.0f;
            for (int k = 0; k < CH; k++)
                acc = __fmaf_rn(zrow[wid][k], __ldg(&e[k]), acc);
            float dd = __fsub_rn(__fadd_rn(s1, __ldg(&g_enorm[j])), __fmul_rn(2.0f, acc));
            if (dd < d) { d = dd; bj = j; }   // j ascends per lane
        }
    }
#pragma unroll
    for (int off = 16; off; off >>= 1) {
        float od = __shfl_xor_sync(0xffffffffu, d, off);
        int oj = __shfl_xor_sync(0xffffffffu, bj, off);
        if (od < d || (od == d && oj < bj)) { d = od; bj = oj; }
    }
    if (lane == 0) g_idx[n] = bj;
}

// ---------------------------------------------------------------------------
// Kernel C: gather z_q with STE arithmetic (out = z + (z_q - z)), per-block
// SSE partial, histogram, idx tail. Block = one (b,h), 256 threads.
// ---------------------------------------------------------------------------
__global__ void k_gather(const float* __restrict__ z, const float* __restrict__ emb,
                         float* __restrict__ out, int out_size) {
    extern __shared__ float sm[];   // s_emb [64][257]
    __shared__ int s_idx[64];
    __shared__ float sred[256];

    const int tid = threadIdx.x;
    const int bid = blockIdx.x;
    const int b = bid >> 6, h = bid & 63;

    if (tid < 64) s_idx[tid] = g_idx[bid * 64 + tid];
    __syncthreads();

#pragma unroll
    for (int i = 0; i < 64; i++) {
        sm[i * 257 + tid] = emb[(size_t)s_idx[i] * CH + tid];
    }
    if (tid < 64) atomicAdd(&g_counts[s_idx[tid]], 1);
    __syncthreads();

    const float* zb = z + (size_t)b * CH * 4096 + (size_t)h * 64;
    float* ob = out + (size_t)b * CH * 4096 + (size_t)h * 64;

    float accum = 0.0f;
#pragma unroll
    for (int i = 0; i < 64; i++) {
        int l = i * 256 + tid;
        int c = l >> 6, w = l & 63;
        float zq = sm[w * 257 + c];
        size_t off = (size_t)c * 4096 + w;
        float zv = zb[off];
        float dd = __fsub_rn(zq, zv);
        ob[off] = __fadd_rn(zv, dd);           // STE: z + (z_q - z)
        accum = __fmaf_rn(dd, dd, accum);
    }
    sred[tid] = accum;
    __syncthreads();
    for (int s = 128; s > 0; s >>= 1) {
        if (tid < s) sred[tid] += sred[tid + s];
        __syncthreads();
    }
    if (tid == 0) g_loss_partial[bid] = sred[0];

    if (tid < 64) {
        int nn = bid * 64 + tid;
        long long pos = (long long)ZQ_ELEMS + 2 + nn;
        if (pos < (long long)out_size) out[pos] = (float)s_idx[tid];
    }
}

// ---------------------------------------------------------------------------
// Kernel D: finalize loss + perplexity.
// ---------------------------------------------------------------------------
__global__ void k_final(float* __restrict__ out, int out_size) {
    __shared__ float sl[1024];
    __shared__ float se[1024];
    int t = threadIdx.x;
    float lp = g_loss_partial[t];
    float em = (float)g_counts[t] / (float)NTOK;
    float ent = -em * logf(em + 1e-10f);
    sl[t] = lp;
    se[t] = ent;
    __syncthreads();
    for (int s = 512; s > 0; s >>= 1) {
        if (t < s) { sl[t] += sl[t + s]; se[t] += se[t + s]; }
        __syncthreads();
    }
    if (t == 0) {
        float m = sl[0] / (float)ZQ_ELEMS;
        if (out_size > ZQ_ELEMS)     out[ZQ_ELEMS]     = __fmaf_rn(0.25f, m, m);
        if (out_size > ZQ_ELEMS + 1) out[ZQ_ELEMS + 1] = expf(se[0]);
    }
}

// ---------------------------------------------------------------------------
extern "C" void kernel_launch(void* const* d_in, const int* in_sizes, int n_in,
                              void* d_out, int out_size) {
    const float* z = (const float*)d_in[0];
    const float* emb = (const float*)d_in[1];
    if (n_in >= 2 && in_sizes[0] == NE * CH) {
        const float* t = z; z = emb; emb = t;
    }
    float* out = (float*)d_out;

    const int SMEM_SCR = (64 * ZSTR + 128 * ESTR) * 2;   // 101376 B dynamic
    const int SMEM_GATH = 64 * 257 * 4;                   // 65792 B
    cudaFuncSetAttribute(k_screen, cudaFuncAttributeMaxDynamicSharedMemorySize, SMEM_SCR);
    cudaFuncSetAttribute(k_gather, cudaFuncAttributeMaxDynamicSharedMemorySize, SMEM_GATH);

    k_enorm<<<NE, 32>>>(emb);
    k_screen<<<1024, 256, SMEM_SCR>>>(z);
    k_exact<<<NTOK / 8, 256>>>(z, emb);
    k_gather<<<1024, 256, SMEM_GATH>>>(z, emb, out, out_size);
    k_final<<<1, 1024>>>(out, out_size);
}

// round 14
// speedup vs baseline: 1.2874x; 1.0284x over previous
#include <cuda_runtime.h>
#include <cuda_bf16.h>
#include <math.h>
#include <float.h>

// Problem constants
#define NB 16
#define CH 256
#define HH 64
#define WW 64
#define NE 1024
#define NTOK (NB*HH*WW)          // 65536
#define ZQ_ELEMS (NB*CH*HH*WW)   // 16777216

// Screening geometry
#define ZSTR 264                 // zbf row stride (bf16)  (528B: LDSM conflict-free)
#define ESTR2 136                // esm row stride (bf16)  (272B: LDSM conflict-free)
#define MARGIN 5.0e-3f           // >= 2*worst-case screen err (3.2e-3); safety

// Scratch (device globals; no allocations allowed)
__device__ float    g_enorm[NE];
__device__ int      g_idx[NTOK];
__device__ float    g_loss_partial[1024];
__device__ int      g_counts[NE];
__device__ __align__(16) __nv_bfloat16 g_ebf[NE*CH];
__device__ unsigned g_mask[(size_t)NTOK*32];   // 1024-bit candidate mask / token

// Monotonic float<->uint encoding for atomicMin on floats
__device__ __forceinline__ unsigned fenc(float f) {
    unsigned u = __float_as_uint(f);
    return (u & 0x80000000u) ? ~u : (u | 0x80000000u);
}
__device__ __forceinline__ float fdec(unsigned e) {
    unsigned u = (e & 0x80000000u) ? (e & 0x7fffffffu) : ~e;
    return __uint_as_float(u);
}

__device__ __forceinline__ void mma16816(float* d,
    unsigned a0, unsigned a1, unsigned a2, unsigned a3,
    unsigned b0, unsigned b1) {
    asm volatile(
        "mma.sync.aligned.m16n8k16.row.col.f32.bf16.bf16.f32 "
        "{%0,%1,%2,%3},{%4,%5,%6,%7},{%8,%9},{%0,%1,%2,%3};"
        : "+f"(d[0]), "+f"(d[1]), "+f"(d[2]), "+f"(d[3])
        : "r"(a0), "r"(a1), "r"(a2), "r"(a3), "r"(b0), "r"(b1));
}

__device__ __forceinline__ void ldsm4(unsigned& r0, unsigned& r1,
                                      unsigned& r2, unsigned& r3, unsigned addr) {
    asm volatile("ldmatrix.sync.aligned.m8n8.x4.shared.b16 {%0,%1,%2,%3}, [%4];"
        : "=r"(r0), "=r"(r1), "=r"(r2), "=r"(r3) : "r"(addr));
}

// ---------------------------------------------------------------------------
// Kernel A: ||e_j||^2 (sequential fp32: rounded mul then add); bf16 copy of
// the codebook; zero histogram.
// ---------------------------------------------------------------------------
__global__ void k_enorm(const float* __restrict__ emb) {
    __shared__ float s[256];
    int j = blockIdx.x, t = threadIdx.x;
    for (int c = t; c < CH; c += 32) s[c] = emb[(size_t)j * CH + c];
    __syncthreads();
    for (int c = t; c < CH; c += 32)
        g_ebf[(size_t)j * CH + c] = __float2bfloat16(s[c]);
    if (t == 0) {
        float acc = 0.0f;
        for (int c = 0; c < CH; c++)
            acc = __fadd_rn(acc, __fmul_rn(s[c], s[c]));
        g_enorm[j] = acc;
        g_counts[j] = 0;
    }
}

// ---------------------------------------------------------------------------
// Kernel B1: tensor-core screening (ldmatrix + mma.sync bf16, fp32 accum).
// Block = 64 tokens (one (b,h) row); 1024 codes in 8 passes of 128, each pass
// in 2 K-chunks of 128 (esm smem halved -> 2 blocks/SM).
// c~ = enorm_j - 2*G~. Every j with c~ <= runningmin + MARGIN sets its bit in
// the per-token candidate mask (guaranteed superset of the exact winner).
// ---------------------------------------------------------------------------
__global__ void __launch_bounds__(256, 2)
k_screen(const float* __restrict__ z) {
    extern __shared__ __nv_bfloat16 smb[];
    __nv_bfloat16* zbf = smb;               // [64][ZSTR]   33792 B
    __nv_bfloat16* esm = smb + 64 * ZSTR;   // [128][ESTR2] 34816 B
    __shared__ unsigned runmin[64];
    __shared__ unsigned smask[64 * 32];

    const int tid = threadIdx.x, lane = tid & 31, wid = tid >> 5;
    const int wm = wid >> 1, wn = wid & 1;
    const int bid = blockIdx.x, b = bid >> 6, h = bid & 63;
    const float* zb = z + (size_t)b * CH * 4096 + (size_t)h * 64;

    // Load + convert z tile -> zbf[token][k] (coalesced gmem reads)
#pragma unroll
    for (int i = 0; i < 64; i++) {
        int l = i * 256 + tid, c = l >> 6, w = l & 63;
        zbf[w * ZSTR + c] = __float2bfloat16(zb[(size_t)c * 4096 + w]);
    }
    if (tid < 64) runmin[tid] = 0xffffffffu;
    for (int i = tid; i < 64 * 32; i += 256) smask[i] = 0u;

    // ldmatrix lane addresses
    const unsigned zbase = (unsigned)__cvta_generic_to_shared(zbf);
    const unsigned ebase = (unsigned)__cvta_generic_to_shared(esm);
    const int grp = lane >> 3, r = lane & 7;
    // A tiles: a0=(rows wm*16+0..7,k0-7) a1=(+8,k0-7) a2=(0..7,k8-15) a3=(+8,k8-15)
    const int arow = wm * 16 + ((grp & 1) << 3) + r;
    const int akoff = (grp >> 1) << 3;
    const unsigned addrA0 = zbase + (unsigned)(arow * ZSTR + akoff) * 2u;
    // B tiles per nt-pair t: (ntA,k0-7)(ntA,k8-15)(ntB,k0-7)(ntB,k8-15)
    const int bkoff = (grp & 1) << 3;
    const int bsel = grp >> 1;
    unsigned addrB0[4];
#pragma unroll
    for (int t = 0; t < 4; t++) {
        int code = wn * 64 + (2 * t + bsel) * 8 + r;
        addrB0[t] = ebase + (unsigned)(code * ESTR2 + bkoff) * 2u;
    }

    const int tokr = wm * 16 + (lane >> 2);
    const int kql = (lane & 3) * 2;

    for (int pass = 0; pass < 8; pass++) {
        const int jbase = pass * 128;
        float dacc[8][4];
#pragma unroll
        for (int nt = 0; nt < 8; nt++)
#pragma unroll
            for (int c2 = 0; c2 < 4; c2++) dacc[nt][c2] = 0.0f;

        for (int chunk = 0; chunk < 2; chunk++) {
            __syncthreads();
            {   // stage 128 codes x 128 k (bf16) into esm
                int row = tid >> 1, half = tid & 1;
                const uint4* src = (const uint4*)(g_ebf
                    + (size_t)(jbase + row) * CH + chunk * 128 + half * 64);
                uint4* dst = (uint4*)(esm + row * ESTR2 + half * 64);
#pragma unroll
                for (int i = 0; i < 8; i++) dst[i] = src[i];
            }
            __syncthreads();

#pragma unroll
            for (int kk2 = 0; kk2 < 8; kk2++) {
                const int kk = chunk * 8 + kk2;
                unsigned a0, a1, a2, a3;
                ldsm4(a0, a1, a2, a3, addrA0 + (unsigned)kk * 32u);
#pragma unroll
                for (int t = 0; t < 4; t++) {
                    unsigned b0, b1, b2, b3;
                    ldsm4(b0, b1, b2, b3, addrB0[t] + (unsigned)kk2 * 32u);
                    mma16816(dacc[2 * t],     a0, a1, a2, a3, b0, b1);
                    mma16816(dacc[2 * t + 1], a0, a1, a2, a3, b2, b3);
                }
            }
        }

        // Epilogue: c~ values, per-token running min, candidate bitmask
        float cv[16], cw[16];
        float m0 = FLT_MAX, m1 = FLT_MAX;
#pragma unroll
        for (int nt = 0; nt < 8; nt++) {
#pragma unroll
            for (int c2 = 0; c2 < 2; c2++) {
                int j = jbase + wn * 64 + nt * 8 + kql + c2;
                float en = __ldg(&g_enorm[j]);
                float v0 = en - 2.0f * dacc[nt][c2];       // row tokr
                float v1 = en - 2.0f * dacc[nt][2 + c2];   // row tokr+8
                cv[nt * 2 + c2] = v0; cw[nt * 2 + c2] = v1;
                m0 = fminf(m0, v0); m1 = fminf(m1, v1);
            }
        }
        m0 = fminf(m0, __shfl_xor_sync(0xffffffffu, m0, 1));
        m0 = fminf(m0, __shfl_xor_sync(0xffffffffu, m0, 2));
        m1 = fminf(m1, __shfl_xor_sync(0xffffffffu, m1, 1));
        m1 = fminf(m1, __shfl_xor_sync(0xffffffffu, m1, 2));
        if ((lane & 3) == 0) {
            atomicMin(&runmin[tokr], fenc(m0));
            atomicMin(&runmin[tokr + 8], fenc(m1));
        }
        __syncthreads();
        float thr0 = fdec(runmin[tokr]) + MARGIN;
        float thr1 = fdec(runmin[tokr + 8]) + MARGIN;
#pragma unroll
        for (int i = 0; i < 16; i++) {
            int j = jbase + wn * 64 + (i >> 1) * 8 + kql + (i & 1);
            if (cv[i] <= thr0)
                atomicOr(&smask[tokr * 32 + (j >> 5)], 1u << (j & 31));
            if (cw[i] <= thr1)
                atomicOr(&smask[(tokr + 8) * 32 + (j >> 5)], 1u << (j & 31));
        }
    }
    __syncthreads();
    for (int i = tid; i < 64 * 32; i += 256)
        g_mask[(size_t)bid * 2048 + i] = smask[i];
}

// ---------------------------------------------------------------------------
// Kernel B2: exact rescue via candidate bitmask. Warp per token; lane owns
// one 32-code mask word and recomputes the frozen reference numerics
// d = fl(fl(s1+en) - 2*G) (sequential ascending-k fp32 FMA chain) for each
// set bit; lexicographic (d, j) warp argmin. No caps, no fallback.
// ---------------------------------------------------------------------------
__global__ void __launch_bounds__(256)
k_exact(const float* __restrict__ z, const float* __restrict__ emb) {
    __shared__ float zrow[8][CH];
    const int tid = threadIdx.x, lane = tid & 31, wid = tid >> 5;
    const int n0 = blockIdx.x * 8;
    const int n = n0 + wid;
    const int b = n0 >> 12, h = (n0 >> 6) & 63, w0 = n0 & 63;
    const float* zb = z + (size_t)b * CH * 4096 + (size_t)h * 64 + w0;

    // Cooperative coalesced stage: zrow[tok][c]
#pragma unroll
    for (int i = 0; i < 8; i++) {
        int idx = i * 256 + tid, c = idx >> 3, t8 = idx & 7;
        zrow[t8][c] = zb[(size_t)c * 4096 + t8];
    }
    __syncthreads();

    // s1 (all lanes redundantly; reference sequential order)
    float s1 = 0.0f;
    for (int k = 0; k < CH; k++) {
        float v = zrow[wid][k];
        s1 = __fadd_rn(s1, __fmul_rn(v, v));
    }

    unsigned m = g_mask[(size_t)n * 32 + lane];
    float d = FLT_MAX; int bj = 0x7fffffff;
    while (m) {
        int bit = __ffs(m) - 1;
        m &= m - 1;
        int j = lane * 32 + bit;
        const float* e = emb + (size_t)j * CH;
        float acc = 0.0f;
#pragma unroll 8
        for (int k = 0; k < CH; k++)
            acc = __fmaf_rn(zrow[wid][k], __ldg(&e[k]), acc);
        float dd = __fsub_rn(__fadd_rn(s1, __ldg(&g_enorm[j])), __fmul_rn(2.0f, acc));
        if (dd < d || (dd == d && j < bj)) { d = dd; bj = j; }
    }
#pragma unroll
    for (int off = 16; off; off >>= 1) {
        float od = __shfl_xor_sync(0xffffffffu, d, off);
        int oj = __shfl_xor_sync(0xffffffffu, bj, off);
        if (od < d || (od == d && oj < bj)) { d = od; bj = oj; }
    }
    if (lane == 0) g_idx[n] = bj;
}

// ---------------------------------------------------------------------------
// Kernel C: gather z_q with STE arithmetic (out = z + (z_q - z)), float4
// vectorized; per-block SSE partial, histogram, idx tail.
// ---------------------------------------------------------------------------
__global__ void k_gather(const float* __restrict__ z, const float* __restrict__ emb,
                         float* __restrict__ out, int out_size) {
    extern __shared__ float sm[];   // s_emb [64][257]
    __shared__ int s_idx[64];
    __shared__ float sred[256];

    const int tid = threadIdx.x;
    const int bid = blockIdx.x;
    const int b = bid >> 6, h = bid & 63;

    if (tid < 64) s_idx[tid] = g_idx[bid * 64 + tid];
    __syncthreads();

#pragma unroll
    for (int i = 0; i < 64; i++) {
        sm[i * 257 + tid] = emb[(size_t)s_idx[i] * CH + tid];
    }
    if (tid < 64) atomicAdd(&g_counts[s_idx[tid]], 1);
    __syncthreads();

    const float* zb = z + (size_t)b * CH * 4096 + (size_t)h * 64;
    float* ob = out + (size_t)b * CH * 4096 + (size_t)h * 64;

    float accum = 0.0f;
#pragma unroll
    for (int i = 0; i < 16; i++) {
        int idx = i * 256 + tid;
        int c = idx >> 4, q = (idx & 15) * 4;
        float4 zq4 = make_float4(sm[q * 257 + c], sm[(q + 1) * 257 + c],
                                 sm[(q + 2) * 257 + c], sm[(q + 3) * 257 + c]);
        size_t off = (size_t)c * 4096 + q;
        float4 zv4 = *(const float4*)&zb[off];
        float d0 = __fsub_rn(zq4.x, zv4.x);
        float d1 = __fsub_rn(zq4.y, zv4.y);
        float d2 = __fsub_rn(zq4.z, zv4.z);
        float d3 = __fsub_rn(zq4.w, zv4.w);
        float4 o4 = make_float4(__fadd_rn(zv4.x, d0), __fadd_rn(zv4.y, d1),
                                __fadd_rn(zv4.z, d2), __fadd_rn(zv4.w, d3));
        *(float4*)&ob[off] = o4;
        accum = __fmaf_rn(d0, d0, accum);
        accum = __fmaf_rn(d1, d1, accum);
        accum = __fmaf_rn(d2, d2, accum);
        accum = __fmaf_rn(d3, d3, accum);
    }
    sred[tid] = accum;
    __syncthreads();
    for (int s = 128; s > 0; s >>= 1) {
        if (tid < s) sred[tid] += sred[tid + s];
        __syncthreads();
    }
    if (tid == 0) g_loss_partial[bid] = sred[0];

    if (tid < 64) {
        int nn = bid * 64 + tid;
        long long pos = (long long)ZQ_ELEMS + 2 + nn;
        if (pos < (long long)out_size) out[pos] = (float)s_idx[tid];
    }
}

// ---------------------------------------------------------------------------
// Kernel D: finalize loss + perplexity.
// ---------------------------------------------------------------------------
__global__ void k_final(float* __restrict__ out, int out_size) {
    __shared__ float sl[1024];
    __shared__ float se[1024];
    int t = threadIdx.x;
    float lp = g_loss_partial[t];
    float em = (float)g_counts[t] / (float)NTOK;
    float ent = -em * logf(em + 1e-10f);
    sl[t] = lp;
    se[t] = ent;
    __syncthreads();
    for (int s = 512; s > 0; s >>= 1) {
        if (t < s) { sl[t] += sl[t + s]; se[t] += se[t + s]; }
        __syncthreads();
    }
    if (t == 0) {
        float m = sl[0] / (float)ZQ_ELEMS;
        if (out_size > ZQ_ELEMS)     out[ZQ_ELEMS]     = __fmaf_rn(0.25f, m, m);
        if (out_size > ZQ_ELEMS + 1) out[ZQ_ELEMS + 1] = expf(se[0]);
    }
}

// ---------------------------------------------------------------------------
extern "C" void kernel_launch(void* const* d_in, const int* in_sizes, int n_in,
                              void* d_out, int out_size) {
    const float* z = (const float*)d_in[0];
    const float* emb = (const float*)d_in[1];
    if (n_in >= 2 && in_sizes[0] == NE * CH) {
        const float* t = z; z = emb; emb = t;
    }
    float* out = (float*)d_out;

    const int SMEM_SCR = (64 * ZSTR + 128 * ESTR2) * 2;  // 68608 B dynamic
    const int SMEM_GATH = 64 * 257 * 4;                   // 65792 B
    cudaFuncSetAttribute(k_screen, cudaFuncAttributeMaxDynamicSharedMemorySize, SMEM_SCR);
    cudaFuncSetAttribute(k_gather, cudaFuncAttributeMaxDynamicSharedMemorySize, SMEM_GATH);

    k_enorm<<<NE, 32>>>(emb);
    k_screen<<<1024, 256, SMEM_SCR>>>(z);
    k_exact<<<NTOK / 8, 256>>>(z, emb);
    k_gather<<<1024, 256, SMEM_GATH>>>(z, emb, out, out_size);
    k_final<<<1, 1024>>>(out, out_size);
}